// round 13
// baseline (speedup 1.0000x reference)
#include <cuda_runtime.h>
#include <cuda_bf16.h>
#include <math.h>
#include <cstdint>

#define B_ 4
#define L_ 2048
#define D_ 1024
#define H_ 16
#define DK_ 64

// ---------------------------------------------------------------------------
// Device scratch
// ---------------------------------------------------------------------------
__device__ unsigned g_mask[B_*L_*(L_/32)];   // 2 MB bit-packed mask
__device__ __nv_bfloat16 g_in_hi[3u*B_*L_*D_];   // q,k,v inputs [sel][m][d]
__device__ __nv_bfloat16 g_in_lo[3u*B_*L_*D_];
__device__ __nv_bfloat16 g_w_hi[4u*D_*D_];       // Wq,Wk,Wv (head-wise), Wo (row-major)
__device__ __nv_bfloat16 g_w_lo[4u*D_*D_];
__device__ __nv_bfloat16 g_mo_hi[B_*L_*D_];      // attention out hi/lo [m][d]
__device__ __nv_bfloat16 g_mo_lo[B_*L_*D_];
__device__ __nv_bfloat16 g_q_hi[B_*H_*L_*DK_];   // [b,h,s,k]
__device__ __nv_bfloat16 g_q_lo[B_*H_*L_*DK_];
__device__ __nv_bfloat16 g_k_hi[B_*H_*L_*DK_];
__device__ __nv_bfloat16 g_k_lo[B_*H_*L_*DK_];
__device__ __nv_bfloat16 g_v_hi[B_*H_*L_*DK_];
__device__ __nv_bfloat16 g_v_lo[B_*H_*L_*DK_];

// ---------------------------------------------------------------------------
// primitives
// ---------------------------------------------------------------------------
__device__ __forceinline__ uint32_t smem_to_u32(const void* p) {
    uint32_t a;
    asm("{ .reg .u64 t; cvta.to.shared.u64 t, %1; cvt.u32.u64 %0, t; }" : "=r"(a) : "l"(p));
    return a;
}
__device__ __forceinline__ void ldsm4(uint32_t d[4], uint32_t addr) {
    asm volatile("ldmatrix.sync.aligned.m8n8.x4.shared.b16 {%0,%1,%2,%3}, [%4];"
        : "=r"(d[0]), "=r"(d[1]), "=r"(d[2]), "=r"(d[3]) : "r"(addr));
}
__device__ __forceinline__ void ldsm4t(uint32_t d[4], uint32_t addr) {
    asm volatile("ldmatrix.sync.aligned.m8n8.x4.trans.shared.b16 {%0,%1,%2,%3}, [%4];"
        : "=r"(d[0]), "=r"(d[1]), "=r"(d[2]), "=r"(d[3]) : "r"(addr));
}
__device__ __forceinline__ void mma_bf16(float c[4], const uint32_t a[4], const uint32_t b[2]) {
    asm volatile("mma.sync.aligned.m16n8k16.row.col.f32.bf16.bf16.f32 "
        "{%0,%1,%2,%3}, {%4,%5,%6,%7}, {%8,%9}, {%0,%1,%2,%3};"
        : "+f"(c[0]), "+f"(c[1]), "+f"(c[2]), "+f"(c[3])
        : "r"(a[0]), "r"(a[1]), "r"(a[2]), "r"(a[3]), "r"(b[0]), "r"(b[1]));
}
__device__ __forceinline__ uint32_t pack_bf16(float x, float y) {
    __nv_bfloat162 t = __floats2bfloat162_rn(x, y);
    return *reinterpret_cast<uint32_t*>(&t);
}
__device__ __forceinline__ void cp16(uint32_t dst, const void* src) {
    asm volatile("cp.async.cg.shared.global [%0], [%1], 16;" :: "r"(dst), "l"(src) : "memory");
}
#define CP_COMMIT() asm volatile("cp.async.commit_group;" ::: "memory")
#define CP_WAIT1()  asm volatile("cp.async.wait_group 1;" ::: "memory")
#define CP_WAIT0()  asm volatile("cp.async.wait_group 0;" ::: "memory")

// ---------------------------------------------------------------------------
// Mask bit-pack
// ---------------------------------------------------------------------------
__global__ void pack_mask_kernel(const int* __restrict__ mask) {
    int idx = blockIdx.x * blockDim.x + threadIdx.x;
    int v = mask[idx];
    unsigned bits = __ballot_sync(0xffffffffu, v != 0);
    if ((threadIdx.x & 31) == 0) g_mask[idx >> 5] = bits;
}

// ---------------------------------------------------------------------------
// fp32 -> bf16 hi/lo pre-split. is_w=0: grid.y in 0..2 -> g_in; is_w=1: 0..3 -> g_w
// ---------------------------------------------------------------------------
__global__ void conv_kernel(const float4* __restrict__ p0, const float4* __restrict__ p1,
                            const float4* __restrict__ p2, const float4* __restrict__ p3,
                            int is_w, int n4) {
    int sel = blockIdx.y;
    const float4* src = (sel == 0) ? p0 : (sel == 1) ? p1 : (sel == 2) ? p2 : p3;
    uint2* hi;
    uint2* lo;
    if (is_w) {
        hi = (uint2*)(g_w_hi + (size_t)sel * (D_*D_));
        lo = (uint2*)(g_w_lo + (size_t)sel * (D_*D_));
    } else {
        hi = (uint2*)(g_in_hi + (size_t)sel * (B_*L_*D_));
        lo = (uint2*)(g_in_lo + (size_t)sel * (B_*L_*D_));
    }
    int i = blockIdx.x * blockDim.x + threadIdx.x;
    if (i >= n4) return;
    float4 a = src[i];
    float h0 = __bfloat162float(__float2bfloat16_rn(a.x));
    float h1 = __bfloat162float(__float2bfloat16_rn(a.y));
    float h2 = __bfloat162float(__float2bfloat16_rn(a.z));
    float h3 = __bfloat162float(__float2bfloat16_rn(a.w));
    hi[i] = make_uint2(pack_bf16(h0, h1), pack_bf16(h2, h3));
    lo[i] = make_uint2(pack_bf16(a.x - h0, a.y - h1), pack_bf16(a.z - h2, a.w - h3));
}

// ---------------------------------------------------------------------------
// Tensor-core GEMM (round-10 form), 3-stage cp.async pipeline, ONE sync/iter.
// BM=128 BN=128 BK=32 (x32 iters), 256 thr (8 warps: 4m x 2n).
// mode 0: merged projections — blockIdx.z = which in {0,1,2} (q,k,v).
// mode 1: output projection, A = g_mo hi/lo, +bias -> Cout fp32.
// ---------------------------------------------------------------------------
#define O_GA 0
#define O_GW 49152
#define GEMM_SMEM 98304

__global__ __launch_bounds__(256, 2) void gemm_tc_kernel(
    const float* __restrict__ bias,
    float* __restrict__ Cout,
    int mode)
{
    extern __shared__ char smem[];
    const uint32_t sb = smem_to_u32(smem);
    const int tid = threadIdx.x;
    const int w = tid >> 5;
    const int L = tid & 31;
    const int wm = w >> 1;
    const int wn = w & 1;
    const int m0 = blockIdx.y * 128;
    const int n0 = blockIdx.x * 128;
    const int which = (mode == 0) ? (int)blockIdx.z : 3;

    const __nv_bfloat16* a_hi = (mode == 0) ? g_in_hi + (size_t)which * (B_*L_*D_) : g_mo_hi;
    const __nv_bfloat16* a_lo = (mode == 0) ? g_in_lo + (size_t)which * (B_*L_*D_) : g_mo_lo;
    const __nv_bfloat16* w_hi = g_w_hi + (size_t)which * (D_*D_);
    const __nv_bfloat16* w_lo = g_w_lo + (size_t)which * (D_*D_);

    const int ra_sub = (L & 7) + ((L >> 3) & 1) * 8;
    const int cha_sub = (L >> 4) & 1;
    const int rb_sub = ((L >> 3) & 1) * 8 + (L & 7);
    const int chb_sub = (L >> 4) & 1;

    const int a_r = tid >> 2;
    const int a_c = tid & 3;
    const int w_kr = (tid >> 3) & 31;
    const int w_c = tid & 7;

    float acc[2][8][4];
    #pragma unroll
    for (int mt = 0; mt < 2; mt++)
        #pragma unroll
        for (int nt = 0; nt < 8; nt++)
            #pragma unroll
            for (int e = 0; e < 4; e++) acc[mt][nt][e] = 0.f;

    auto stage = [&](int s, int k0) {
        uint32_t abase = sb + O_GA + s * 16384;
        #pragma unroll
        for (int i = 0; i < 2; i++) {
            int r = a_r + i * 64;
            size_t so = (size_t)(m0 + r) * D_ + k0 + a_c * 8;
            cp16(abase + (uint32_t)(r * 128 + (((a_c    ) ^ (r & 7)) << 4)), a_hi + so);
            cp16(abase + (uint32_t)(r * 128 + (((a_c + 4) ^ (r & 7)) << 4)), a_lo + so);
        }
        uint32_t wbase = sb + O_GW + s * 16384;
        #pragma unroll
        for (int hn = 0; hn < 2; hn++) {
            size_t so;
            if (mode == 0)
                so = (size_t)(2 * blockIdx.x + hn) * (D_ * DK_) + (size_t)(k0 + w_kr) * DK_ + w_c * 8;
            else
                so = (size_t)(k0 + w_kr) * D_ + n0 + hn * 64 + w_c * 8;
            uint32_t doff = (uint32_t)(hn * 4096 + w_kr * 128 + ((w_c ^ (w_kr & 7)) << 4));
            cp16(wbase + doff, w_hi + so);
            cp16(wbase + 8192 + doff, w_lo + so);
        }
        CP_COMMIT();
    };

    stage(0, 0);
    stage(1, 32);

    #pragma unroll 1
    for (int it = 0; it < 32; it++) {
        if (it < 31) { CP_WAIT1(); } else { CP_WAIT0(); }
        __syncthreads();
        if (it + 2 < 32) stage((it + 2) % 3, (it + 2) * 32);

        const int cs = it % 3;
        const uint32_t abase = sb + O_GA + cs * 16384;
        const uint32_t wb_h = sb + O_GW + cs * 16384 + wn * 4096;
        const uint32_t wb_l = wb_h + 8192;

        #pragma unroll
        for (int g = 0; g < 2; g++) {
            uint32_t afh[2][4], afl[2][4];
            #pragma unroll
            for (int mt = 0; mt < 2; mt++) {
                int ra = 32 * wm + 16 * mt + ra_sub;
                int idh = 2 * g + cha_sub;
                uint32_t rbase = abase + (uint32_t)(ra * 128);
                ldsm4(afh[mt], rbase + (uint32_t)(((idh    ) ^ (ra & 7)) << 4));
                ldsm4(afl[mt], rbase + (uint32_t)(((idh + 4) ^ (ra & 7)) << 4));
            }
            #pragma unroll
            for (int tp = 0; tp < 4; tp++) {
                uint32_t bh[4], bl[4];
                int rb = 16 * g + rb_sub;
                int ch = 2 * tp + chb_sub;
                uint32_t boff = (uint32_t)(rb * 128 + ((ch ^ (rb & 7)) << 4));
                ldsm4t(bh, wb_h + boff);
                ldsm4t(bl, wb_l + boff);
                #pragma unroll
                for (int mt = 0; mt < 2; mt++) {
                    mma_bf16(acc[mt][2 * tp],     afh[mt], bh);
                    mma_bf16(acc[mt][2 * tp + 1], afh[mt], bh + 2);
                    mma_bf16(acc[mt][2 * tp],     afh[mt], bl);
                    mma_bf16(acc[mt][2 * tp + 1], afh[mt], bl + 2);
                    mma_bf16(acc[mt][2 * tp],     afl[mt], bh);
                    mma_bf16(acc[mt][2 * tp + 1], afl[mt], bh + 2);
                }
            }
        }
    }

    // ---- epilogue ----
    if (mode == 0) {
        __nv_bfloat16* hi_arr = (which == 0) ? g_q_hi : (which == 1) ? g_k_hi : g_v_hi;
        __nv_bfloat16* lo_arr = (which == 0) ? g_q_lo : (which == 1) ? g_k_lo : g_v_lo;
        const int hh = 2 * blockIdx.x + wn;
        #pragma unroll
        for (int mt = 0; mt < 2; mt++) {
            int m1 = m0 + 32 * wm + 16 * mt + (L >> 2);
            #pragma unroll
            for (int nt = 0; nt < 8; nt++) {
                int kk = nt * 8 + (L & 3) * 2;
                #pragma unroll
                for (int half = 0; half < 2; half++) {
                    int m = m1 + half * 8;
                    int b = m >> 11;
                    int s = m & (L_ - 1);
                    float c0 = acc[mt][nt][2 * half + 0];
                    float c1 = acc[mt][nt][2 * half + 1];
                    float h0 = __bfloat162float(__float2bfloat16_rn(c0));
                    float h1 = __bfloat162float(__float2bfloat16_rn(c1));
                    size_t eidx = (((size_t)(b * H_ + hh) * L_ + s) * DK_ + kk) >> 1;
                    ((uint32_t*)hi_arr)[eidx] = pack_bf16(h0, h1);
                    ((uint32_t*)lo_arr)[eidx] = pack_bf16(c0 - h0, c1 - h1);
                }
            }
        }
    } else {
        #pragma unroll
        for (int mt = 0; mt < 2; mt++) {
            int m1 = m0 + 32 * wm + 16 * mt + (L >> 2);
            #pragma unroll
            for (int nt = 0; nt < 8; nt++) {
                int n = n0 + wn * 64 + nt * 8 + (L & 3) * 2;
                float b0 = bias[n], b1 = bias[n + 1];
                #pragma unroll
                for (int half = 0; half < 2; half++) {
                    int m = m1 + half * 8;
                    float2 v = make_float2(acc[mt][nt][2 * half + 0] + b0,
                                           acc[mt][nt][2 * half + 1] + b1);
                    *(float2*)(Cout + (size_t)m * D_ + n) = v;
                }
            }
        }
    }
}

// ---------------------------------------------------------------------------
// Tensor-core flash attention, cp.async 2-stage K/V pipeline, ONE sync/iter.
// Half-tile pipelining: S(A) -> S(B) -> epi(A)|drain(B) -> PV(A) -> epi(B)|drain(PV A) -> PV(B).
// Accumulation order per register identical to round-10 -> bit-identical output.
// ---------------------------------------------------------------------------
#define QT 128
#define CT 64
#define O_QHI 0
#define O_QLO 16384
#define O_STG 32768          /* + p*32768: KHI 0 / KLO 8192 / VHI 16384 / VLO 24576 */
#define ATTN_SMEM 98304

__global__ __launch_bounds__(256, 2) void attn_mma_kernel() {
    extern __shared__ char smem[];
    const uint32_t sb = smem_to_u32(smem);
    const int tid = threadIdx.x;
    const int w = tid >> 5;
    const int L = tid & 31;
    const int q0 = blockIdx.x * QT;
    const int h = blockIdx.y;
    const int b = blockIdx.z;
    const size_t bh = (size_t)(b * H_ + h);

    {
        const uint4* qh4 = (const uint4*)(g_q_hi + (bh * L_ + q0) * DK_);
        const uint4* ql4 = (const uint4*)(g_q_lo + (bh * L_ + q0) * DK_);
        #pragma unroll
        for (int i = 0; i < 4; i++) {
            int f = i * 256 + tid;
            int r = f >> 3, ch = f & 7;
            uint32_t off = (uint32_t)(r * 128 + ((ch ^ (r & 7)) << 4));
            *(uint4*)(smem + O_QHI + off) = qh4[f];
            *(uint4*)(smem + O_QLO + off) = ql4[f];
        }
    }

    const __nv_bfloat16* kh = g_k_hi + bh * L_ * DK_;
    const __nv_bfloat16* kl = g_k_lo + bh * L_ * DK_;
    const __nv_bfloat16* vh = g_v_hi + bh * L_ * DK_;
    const __nv_bfloat16* vl = g_v_lo + bh * L_ * DK_;

    const int kv_r0 = tid >> 3;
    const int kv_c = tid & 7;

    auto load_kv = [&](int p, int c0) {
        uint32_t base = sb + O_STG + p * 32768;
        #pragma unroll
        for (int i = 0; i < 2; i++) {
            int r = kv_r0 + i * 32;
            size_t so = (size_t)(c0 + r) * DK_ + kv_c * 8;
            uint32_t doff = (uint32_t)(r * 128 + ((kv_c ^ (r & 7)) << 4));
            cp16(base + doff, kh + so);
            cp16(base + 8192 + doff, kl + so);
            cp16(base + 16384 + doff, vh + so);
            cp16(base + 24576 + doff, vl + so);
        }
        CP_COMMIT();
    };

    const int rq = 16 * w + (L & 7) + ((L >> 3) & 1) * 8;
    const int rk_sub = ((L >> 4) & 1) * 8 + (L & 7);
    const int rv_sub = ((L >> 3) & 1) * 8 + (L & 7);
    const int chq_sub = (L >> 4) & 1;
    const int chk_sub = (L >> 3) & 1;
    const int chv_sub = (L >> 4) & 1;

    const int r1 = 16 * w + (L >> 2);
    const unsigned* mp1 = g_mask + (size_t)(b * L_ + q0 + r1) * (L_ / 32);
    const unsigned* mp2 = mp1 + 8 * (L_ / 32);

    float o[8][4];
    #pragma unroll
    for (int t = 0; t < 8; t++)
        #pragma unroll
        for (int e = 0; e < 4; e++) o[t][e] = 0.f;
    float rs1 = 0.f, rs2 = 0.f;

    load_kv(0, 0);

    #pragma unroll 1
    for (int it = 0; it < L_ / CT; it++) {
        int p = it & 1;
        int c0 = it * CT;
        CP_WAIT0();
        __syncthreads();
        if (it + 1 < L_ / CT) load_kv(p ^ 1, c0 + CT);

        const uint32_t kb_h = sb + O_STG + p * 32768;
        const uint32_t kb_l = kb_h + 8192;
        const uint32_t vb_h = kb_h + 16384;
        const uint32_t vb_l = kb_h + 24576;

        float s[8][4];
        #pragma unroll
        for (int t = 0; t < 8; t++)
            #pragma unroll
            for (int e = 0; e < 4; e++) s[t][e] = 0.f;

        // ---- S-MMAs, both halves back-to-back (tensor pipe queues up) ----
        #pragma unroll
        for (int half = 0; half < 2; half++) {
            #pragma unroll
            for (int g = 0; g < 4; g++) {
                uint32_t qh_[4], ql_[4];
                int chq = 2 * g + chq_sub;
                uint32_t qoff = (uint32_t)(rq * 128 + ((chq ^ (rq & 7)) << 4));
                ldsm4(qh_, sb + O_QHI + qoff);
                ldsm4(ql_, sb + O_QLO + qoff);
                #pragma unroll
                for (int tq = 0; tq < 2; tq++) {
                    int tp = half * 2 + tq;
                    uint32_t kh_[4], kl_[4];
                    int rk = 16 * tp + rk_sub;
                    int chk = 2 * g + chk_sub;
                    uint32_t koff = (uint32_t)(rk * 128 + ((chk ^ (rk & 7)) << 4));
                    ldsm4(kh_, kb_h + koff);
                    ldsm4(kl_, kb_l + koff);
                    mma_bf16(s[2 * tp],     qh_, kh_);
                    mma_bf16(s[2 * tp + 1], qh_, kh_ + 2);
                    mma_bf16(s[2 * tp],     qh_, kl_);
                    mma_bf16(s[2 * tp + 1], qh_, kl_ + 2);
                    mma_bf16(s[2 * tp],     ql_, kh_);
                    mma_bf16(s[2 * tp + 1], ql_, kh_ + 2);
                }
            }
        }

        uint2 mwa = *(const uint2*)(mp1 + (c0 >> 5));
        uint2 mwb = *(const uint2*)(mp2 + (c0 >> 5));

        // ---- interleaved: epi(half) then PV(half) — epi overlaps tensor drain ----
        #pragma unroll
        for (int half = 0; half < 2; half++) {
            // epilogue for keys [32*half, 32*half+32): t = 4*half .. 4*half+3
            uint32_t ahi[2][4], alo[2][4];
            #pragma unroll
            for (int tq = 0; tq < 4; tq++) {
                int t = half * 4 + tq;
                unsigned wa = (half == 0) ? mwa.x : mwa.y;
                unsigned wb = (half == 0) ? mwb.x : mwb.y;
                int sh = (tq << 3) + ((L & 3) << 1);
                float p0 = ((wa >> sh) & 1u)       ? __expf(s[t][0] * 0.125f) : 0.f;
                float p1 = ((wa >> (sh + 1)) & 1u) ? __expf(s[t][1] * 0.125f) : 0.f;
                float p2 = ((wb >> sh) & 1u)       ? __expf(s[t][2] * 0.125f) : 0.f;
                float p3 = ((wb >> (sh + 1)) & 1u) ? __expf(s[t][3] * 0.125f) : 0.f;
                rs1 += p0 + p1;
                rs2 += p2 + p3;
                float h0 = __bfloat162float(__float2bfloat16_rn(p0));
                float h1 = __bfloat162float(__float2bfloat16_rn(p1));
                float h2 = __bfloat162float(__float2bfloat16_rn(p2));
                float h3 = __bfloat162float(__float2bfloat16_rn(p3));
                int gl = tq >> 1, e = (tq & 1) * 2;
                ahi[gl][e]     = pack_bf16(h0, h1);
                ahi[gl][e + 1] = pack_bf16(h2, h3);
                alo[gl][e]     = pack_bf16(p0 - h0, p1 - h1);
                alo[gl][e + 1] = pack_bf16(p2 - h2, p3 - h3);
            }
            // PV for this half: g = 2*half + {0,1}
            #pragma unroll
            for (int gl = 0; gl < 2; gl++) {
                int g = half * 2 + gl;
                int rv = 16 * g + rv_sub;
                #pragma unroll
                for (int tp = 0; tp < 4; tp++) {
                    uint32_t vh_[4], vl_[4];
                    int chv = 2 * tp + chv_sub;
                    uint32_t voff = (uint32_t)(rv * 128 + ((chv ^ (rv & 7)) << 4));
                    ldsm4t(vh_, vb_h + voff);
                    ldsm4t(vl_, vb_l + voff);
                    mma_bf16(o[2 * tp],     ahi[gl], vh_);
                    mma_bf16(o[2 * tp + 1], ahi[gl], vh_ + 2);
                    mma_bf16(o[2 * tp],     ahi[gl], vl_);
                    mma_bf16(o[2 * tp + 1], ahi[gl], vl_ + 2);
                    mma_bf16(o[2 * tp],     alo[gl], vh_);
                    mma_bf16(o[2 * tp + 1], alo[gl], vh_ + 2);
                }
            }
        }
    }

    rs1 += __shfl_xor_sync(0xffffffffu, rs1, 1);
    rs1 += __shfl_xor_sync(0xffffffffu, rs1, 2);
    rs2 += __shfl_xor_sync(0xffffffffu, rs2, 1);
    rs2 += __shfl_xor_sync(0xffffffffu, rs2, 2);
    float i1 = 1.f / rs1;
    float i2 = 1.f / rs2;

    size_t row1 = (size_t)(b * L_ + q0 + r1) * D_ + h * DK_;
    size_t row2 = row1 + 8 * D_;
    #pragma unroll
    for (int t = 0; t < 8; t++) {
        int j = 8 * t + ((L & 3) << 1);
        float v0 = o[t][0] * i1, v1 = o[t][1] * i1;
        float v2 = o[t][2] * i2, v3 = o[t][3] * i2;
        float h0 = __bfloat162float(__float2bfloat16_rn(v0));
        float h1 = __bfloat162float(__float2bfloat16_rn(v1));
        float h2 = __bfloat162float(__float2bfloat16_rn(v2));
        float h3 = __bfloat162float(__float2bfloat16_rn(v3));
        ((uint32_t*)g_mo_hi)[(row1 + j) >> 1] = pack_bf16(h0, h1);
        ((uint32_t*)g_mo_lo)[(row1 + j) >> 1] = pack_bf16(v0 - h0, v1 - h1);
        ((uint32_t*)g_mo_hi)[(row2 + j) >> 1] = pack_bf16(h2, h3);
        ((uint32_t*)g_mo_lo)[(row2 + j) >> 1] = pack_bf16(v2 - h2, v3 - h3);
    }
}

// ---------------------------------------------------------------------------
extern "C" void kernel_launch(void* const* d_in, const int* in_sizes, int n_in,
                              void* d_out, int out_size) {
    const float* q   = (const float*)d_in[0];
    const float* k   = (const float*)d_in[1];
    const float* v   = (const float*)d_in[2];
    const int*   msk = (const int*)d_in[3];
    const float* Wq  = (const float*)d_in[4];
    const float* Wk  = (const float*)d_in[5];
    const float* Wv  = (const float*)d_in[6];
    const float* Wo  = (const float*)d_in[7];
    const float* bo  = (const float*)d_in[8];
    float* out = (float*)d_out;

    cudaFuncSetAttribute(attn_mma_kernel,
                         cudaFuncAttributeMaxDynamicSharedMemorySize, ATTN_SMEM);
    cudaFuncSetAttribute(gemm_tc_kernel,
                         cudaFuncAttributeMaxDynamicSharedMemorySize, GEMM_SMEM);

    pack_mask_kernel<<<(B_ * L_ * L_) / 256, 256>>>(msk);

    const int n4_in = (B_ * L_ * D_) / 4;
    const int n4_w  = (D_ * D_) / 4;
    conv_kernel<<<dim3(n4_in / 256, 3), 256>>>((const float4*)q, (const float4*)k,
                                               (const float4*)v, nullptr, 0, n4_in);
    conv_kernel<<<dim3(n4_w / 256, 4), 256>>>((const float4*)Wq, (const float4*)Wk,
                                              (const float4*)Wv, (const float4*)Wo, 1, n4_w);

    gemm_tc_kernel<<<dim3(D_ / 128, (B_ * L_) / 128, 3), 256, GEMM_SMEM>>>(nullptr, nullptr, 0);

    attn_mma_kernel<<<dim3(L_ / QT, H_, B_), 256, ATTN_SMEM>>>();

    gemm_tc_kernel<<<dim3(D_ / 128, (B_ * L_) / 128, 1), 256, GEMM_SMEM>>>(bo, out, 1);
}

// round 14
// speedup vs baseline: 1.0586x; 1.0586x over previous
#include <cuda_runtime.h>
#include <cuda_bf16.h>
#include <math.h>
#include <cstdint>

#define B_ 4
#define L_ 2048
#define D_ 1024
#define H_ 16
#define DK_ 64

// ---------------------------------------------------------------------------
// Device scratch
// ---------------------------------------------------------------------------
__device__ unsigned g_mask[B_*L_*(L_/32)];   // 2 MB bit-packed mask
__device__ __nv_bfloat16 g_in_hi[3u*B_*L_*D_];   // q,k,v inputs [sel][m][d]
__device__ __nv_bfloat16 g_in_lo[3u*B_*L_*D_];
__device__ __nv_bfloat16 g_w_hi[4u*D_*D_];       // Wq,Wk,Wv (head-wise), Wo (row-major)
__device__ __nv_bfloat16 g_w_lo[4u*D_*D_];
__device__ __nv_bfloat16 g_mo_hi[B_*L_*D_];      // attention out hi/lo [m][d]
__device__ __nv_bfloat16 g_mo_lo[B_*L_*D_];
__device__ __nv_bfloat16 g_q_hi[B_*H_*L_*DK_];   // [b,h,s,k]
__device__ __nv_bfloat16 g_q_lo[B_*H_*L_*DK_];
__device__ __nv_bfloat16 g_k_hi[B_*H_*L_*DK_];
__device__ __nv_bfloat16 g_k_lo[B_*H_*L_*DK_];
__device__ __nv_bfloat16 g_v_hi[B_*H_*L_*DK_];
__device__ __nv_bfloat16 g_v_lo[B_*H_*L_*DK_];

// ---------------------------------------------------------------------------
// primitives
// ---------------------------------------------------------------------------
__device__ __forceinline__ uint32_t smem_to_u32(const void* p) {
    uint32_t a;
    asm("{ .reg .u64 t; cvta.to.shared.u64 t, %1; cvt.u32.u64 %0, t; }" : "=r"(a) : "l"(p));
    return a;
}
__device__ __forceinline__ void ldsm4(uint32_t d[4], uint32_t addr) {
    asm volatile("ldmatrix.sync.aligned.m8n8.x4.shared.b16 {%0,%1,%2,%3}, [%4];"
        : "=r"(d[0]), "=r"(d[1]), "=r"(d[2]), "=r"(d[3]) : "r"(addr));
}
__device__ __forceinline__ void ldsm4t(uint32_t d[4], uint32_t addr) {
    asm volatile("ldmatrix.sync.aligned.m8n8.x4.trans.shared.b16 {%0,%1,%2,%3}, [%4];"
        : "=r"(d[0]), "=r"(d[1]), "=r"(d[2]), "=r"(d[3]) : "r"(addr));
}
__device__ __forceinline__ void mma_bf16(float c[4], const uint32_t a[4], const uint32_t b[2]) {
    asm volatile("mma.sync.aligned.m16n8k16.row.col.f32.bf16.bf16.f32 "
        "{%0,%1,%2,%3}, {%4,%5,%6,%7}, {%8,%9}, {%0,%1,%2,%3};"
        : "+f"(c[0]), "+f"(c[1]), "+f"(c[2]), "+f"(c[3])
        : "r"(a[0]), "r"(a[1]), "r"(a[2]), "r"(a[3]), "r"(b[0]), "r"(b[1]));
}
__device__ __forceinline__ uint32_t pack_bf16(float x, float y) {
    __nv_bfloat162 t = __floats2bfloat162_rn(x, y);
    return *reinterpret_cast<uint32_t*>(&t);
}
__device__ __forceinline__ void cp16(uint32_t dst, const void* src) {
    asm volatile("cp.async.cg.shared.global [%0], [%1], 16;" :: "r"(dst), "l"(src) : "memory");
}
#define CP_COMMIT() asm volatile("cp.async.commit_group;" ::: "memory")
#define CP_WAIT1()  asm volatile("cp.async.wait_group 1;" ::: "memory")
#define CP_WAIT0()  asm volatile("cp.async.wait_group 0;" ::: "memory")

// ---------------------------------------------------------------------------
// Mask bit-pack, MLP=4: each warp packs 128 ints -> one uint4 (16B store).
// ---------------------------------------------------------------------------
__global__ void pack_mask_kernel(const int* __restrict__ mask) {
    int lane = threadIdx.x & 31;
    int warp = threadIdx.x >> 5;
    size_t base = (size_t)blockIdx.x * 1024 + (size_t)warp * 128;
    const int* p = mask + base;
    int v0 = p[lane];
    int v1 = p[lane + 32];
    int v2 = p[lane + 64];
    int v3 = p[lane + 96];
    unsigned b0 = __ballot_sync(0xffffffffu, v0 != 0);
    unsigned b1 = __ballot_sync(0xffffffffu, v1 != 0);
    unsigned b2 = __ballot_sync(0xffffffffu, v2 != 0);
    unsigned b3 = __ballot_sync(0xffffffffu, v3 != 0);
    if (lane == 0)
        *(uint4*)(g_mask + (base >> 5)) = make_uint4(b0, b1, b2, b3);
}

// ---------------------------------------------------------------------------
// fp32 -> bf16 hi/lo pre-split, 2 float4 per thread (MLP=2).
// is_w=0: grid.y 0..2 -> g_in; is_w=1: 0..3 -> g_w
// ---------------------------------------------------------------------------
__global__ void conv_kernel(const float4* __restrict__ p0, const float4* __restrict__ p1,
                            const float4* __restrict__ p2, const float4* __restrict__ p3,
                            int is_w, int n4) {
    int sel = blockIdx.y;
    const float4* src = (sel == 0) ? p0 : (sel == 1) ? p1 : (sel == 2) ? p2 : p3;
    uint2* hi;
    uint2* lo;
    if (is_w) {
        hi = (uint2*)(g_w_hi + (size_t)sel * (D_*D_));
        lo = (uint2*)(g_w_lo + (size_t)sel * (D_*D_));
    } else {
        hi = (uint2*)(g_in_hi + (size_t)sel * (B_*L_*D_));
        lo = (uint2*)(g_in_lo + (size_t)sel * (B_*L_*D_));
    }
    int i0 = blockIdx.x * (blockDim.x * 2) + threadIdx.x;
    #pragma unroll
    for (int r = 0; r < 2; r++) {
        int i = i0 + r * blockDim.x;
        if (i >= n4) continue;
        float4 a = src[i];
        float h0 = __bfloat162float(__float2bfloat16_rn(a.x));
        float h1 = __bfloat162float(__float2bfloat16_rn(a.y));
        float h2 = __bfloat162float(__float2bfloat16_rn(a.z));
        float h3 = __bfloat162float(__float2bfloat16_rn(a.w));
        hi[i] = make_uint2(pack_bf16(h0, h1), pack_bf16(h2, h3));
        lo[i] = make_uint2(pack_bf16(a.x - h0, a.y - h1), pack_bf16(a.z - h2, a.w - h3));
    }
}

// ---------------------------------------------------------------------------
// Tensor-core GEMM (round-10 form), 3-stage cp.async pipeline, ONE sync/iter.
// BM=128 BN=128 BK=32 (x32 iters), 256 thr (8 warps: 4m x 2n).
// mode 0: merged projections — blockIdx.z = which in {0,1,2} (q,k,v).
// mode 1: output projection, A = g_mo hi/lo, +bias -> Cout fp32.
// ---------------------------------------------------------------------------
#define O_GA 0
#define O_GW 49152
#define GEMM_SMEM 98304

__global__ __launch_bounds__(256, 2) void gemm_tc_kernel(
    const float* __restrict__ bias,
    float* __restrict__ Cout,
    int mode)
{
    extern __shared__ char smem[];
    const uint32_t sb = smem_to_u32(smem);
    const int tid = threadIdx.x;
    const int w = tid >> 5;
    const int L = tid & 31;
    const int wm = w >> 1;
    const int wn = w & 1;
    const int m0 = blockIdx.y * 128;
    const int n0 = blockIdx.x * 128;
    const int which = (mode == 0) ? (int)blockIdx.z : 3;

    const __nv_bfloat16* a_hi = (mode == 0) ? g_in_hi + (size_t)which * (B_*L_*D_) : g_mo_hi;
    const __nv_bfloat16* a_lo = (mode == 0) ? g_in_lo + (size_t)which * (B_*L_*D_) : g_mo_lo;
    const __nv_bfloat16* w_hi = g_w_hi + (size_t)which * (D_*D_);
    const __nv_bfloat16* w_lo = g_w_lo + (size_t)which * (D_*D_);

    const int ra_sub = (L & 7) + ((L >> 3) & 1) * 8;
    const int cha_sub = (L >> 4) & 1;
    const int rb_sub = ((L >> 3) & 1) * 8 + (L & 7);
    const int chb_sub = (L >> 4) & 1;

    const int a_r = tid >> 2;
    const int a_c = tid & 3;
    const int w_kr = (tid >> 3) & 31;
    const int w_c = tid & 7;

    float acc[2][8][4];
    #pragma unroll
    for (int mt = 0; mt < 2; mt++)
        #pragma unroll
        for (int nt = 0; nt < 8; nt++)
            #pragma unroll
            for (int e = 0; e < 4; e++) acc[mt][nt][e] = 0.f;

    auto stage = [&](int s, int k0) {
        uint32_t abase = sb + O_GA + s * 16384;
        #pragma unroll
        for (int i = 0; i < 2; i++) {
            int r = a_r + i * 64;
            size_t so = (size_t)(m0 + r) * D_ + k0 + a_c * 8;
            cp16(abase + (uint32_t)(r * 128 + (((a_c    ) ^ (r & 7)) << 4)), a_hi + so);
            cp16(abase + (uint32_t)(r * 128 + (((a_c + 4) ^ (r & 7)) << 4)), a_lo + so);
        }
        uint32_t wbase = sb + O_GW + s * 16384;
        #pragma unroll
        for (int hn = 0; hn < 2; hn++) {
            size_t so;
            if (mode == 0)
                so = (size_t)(2 * blockIdx.x + hn) * (D_ * DK_) + (size_t)(k0 + w_kr) * DK_ + w_c * 8;
            else
                so = (size_t)(k0 + w_kr) * D_ + n0 + hn * 64 + w_c * 8;
            uint32_t doff = (uint32_t)(hn * 4096 + w_kr * 128 + ((w_c ^ (w_kr & 7)) << 4));
            cp16(wbase + doff, w_hi + so);
            cp16(wbase + 8192 + doff, w_lo + so);
        }
        CP_COMMIT();
    };

    stage(0, 0);
    stage(1, 32);

    #pragma unroll 1
    for (int it = 0; it < 32; it++) {
        if (it < 31) { CP_WAIT1(); } else { CP_WAIT0(); }
        __syncthreads();
        if (it + 2 < 32) stage((it + 2) % 3, (it + 2) * 32);

        const int cs = it % 3;
        const uint32_t abase = sb + O_GA + cs * 16384;
        const uint32_t wb_h = sb + O_GW + cs * 16384 + wn * 4096;
        const uint32_t wb_l = wb_h + 8192;

        #pragma unroll
        for (int g = 0; g < 2; g++) {
            uint32_t afh[2][4], afl[2][4];
            #pragma unroll
            for (int mt = 0; mt < 2; mt++) {
                int ra = 32 * wm + 16 * mt + ra_sub;
                int idh = 2 * g + cha_sub;
                uint32_t rbase = abase + (uint32_t)(ra * 128);
                ldsm4(afh[mt], rbase + (uint32_t)(((idh    ) ^ (ra & 7)) << 4));
                ldsm4(afl[mt], rbase + (uint32_t)(((idh + 4) ^ (ra & 7)) << 4));
            }
            #pragma unroll
            for (int tp = 0; tp < 4; tp++) {
                uint32_t bh[4], bl[4];
                int rb = 16 * g + rb_sub;
                int ch = 2 * tp + chb_sub;
                uint32_t boff = (uint32_t)(rb * 128 + ((ch ^ (rb & 7)) << 4));
                ldsm4t(bh, wb_h + boff);
                ldsm4t(bl, wb_l + boff);
                #pragma unroll
                for (int mt = 0; mt < 2; mt++) {
                    mma_bf16(acc[mt][2 * tp],     afh[mt], bh);
                    mma_bf16(acc[mt][2 * tp + 1], afh[mt], bh + 2);
                    mma_bf16(acc[mt][2 * tp],     afh[mt], bl);
                    mma_bf16(acc[mt][2 * tp + 1], afh[mt], bl + 2);
                    mma_bf16(acc[mt][2 * tp],     afl[mt], bh);
                    mma_bf16(acc[mt][2 * tp + 1], afl[mt], bh + 2);
                }
            }
        }
    }

    // ---- epilogue ----
    if (mode == 0) {
        __nv_bfloat16* hi_arr = (which == 0) ? g_q_hi : (which == 1) ? g_k_hi : g_v_hi;
        __nv_bfloat16* lo_arr = (which == 0) ? g_q_lo : (which == 1) ? g_k_lo : g_v_lo;
        const int hh = 2 * blockIdx.x + wn;
        #pragma unroll
        for (int mt = 0; mt < 2; mt++) {
            int m1 = m0 + 32 * wm + 16 * mt + (L >> 2);
            #pragma unroll
            for (int nt = 0; nt < 8; nt++) {
                int kk = nt * 8 + (L & 3) * 2;
                #pragma unroll
                for (int half = 0; half < 2; half++) {
                    int m = m1 + half * 8;
                    int b = m >> 11;
                    int s = m & (L_ - 1);
                    float c0 = acc[mt][nt][2 * half + 0];
                    float c1 = acc[mt][nt][2 * half + 1];
                    float h0 = __bfloat162float(__float2bfloat16_rn(c0));
                    float h1 = __bfloat162float(__float2bfloat16_rn(c1));
                    size_t eidx = (((size_t)(b * H_ + hh) * L_ + s) * DK_ + kk) >> 1;
                    ((uint32_t*)hi_arr)[eidx] = pack_bf16(h0, h1);
                    ((uint32_t*)lo_arr)[eidx] = pack_bf16(c0 - h0, c1 - h1);
                }
            }
        }
    } else {
        #pragma unroll
        for (int mt = 0; mt < 2; mt++) {
            int m1 = m0 + 32 * wm + 16 * mt + (L >> 2);
            #pragma unroll
            for (int nt = 0; nt < 8; nt++) {
                int n = n0 + wn * 64 + nt * 8 + (L & 3) * 2;
                float b0 = bias[n], b1 = bias[n + 1];
                #pragma unroll
                for (int half = 0; half < 2; half++) {
                    int m = m1 + half * 8;
                    float2 v = make_float2(acc[mt][nt][2 * half + 0] + b0,
                                           acc[mt][nt][2 * half + 1] + b1);
                    *(float2*)(Cout + (size_t)m * D_ + n) = v;
                }
            }
        }
    }
}

// ---------------------------------------------------------------------------
// Tensor-core flash attention (round-10 form): cp.async 2-stage K/V pipeline,
// ONE sync/iter, no fragment hoisting/double-buffering, straight S->epi->PV.
// ---------------------------------------------------------------------------
#define QT 128
#define CT 64
#define O_QHI 0
#define O_QLO 16384
#define O_STG 32768          /* + p*32768: KHI 0 / KLO 8192 / VHI 16384 / VLO 24576 */
#define ATTN_SMEM 98304

__global__ __launch_bounds__(256, 2) void attn_mma_kernel() {
    extern __shared__ char smem[];
    const uint32_t sb = smem_to_u32(smem);
    const int tid = threadIdx.x;
    const int w = tid >> 5;
    const int L = tid & 31;
    const int q0 = blockIdx.x * QT;
    const int h = blockIdx.y;
    const int b = blockIdx.z;
    const size_t bh = (size_t)(b * H_ + h);

    {
        const uint4* qh4 = (const uint4*)(g_q_hi + (bh * L_ + q0) * DK_);
        const uint4* ql4 = (const uint4*)(g_q_lo + (bh * L_ + q0) * DK_);
        #pragma unroll
        for (int i = 0; i < 4; i++) {
            int f = i * 256 + tid;
            int r = f >> 3, ch = f & 7;
            uint32_t off = (uint32_t)(r * 128 + ((ch ^ (r & 7)) << 4));
            *(uint4*)(smem + O_QHI + off) = qh4[f];
            *(uint4*)(smem + O_QLO + off) = ql4[f];
        }
    }

    const __nv_bfloat16* kh = g_k_hi + bh * L_ * DK_;
    const __nv_bfloat16* kl = g_k_lo + bh * L_ * DK_;
    const __nv_bfloat16* vh = g_v_hi + bh * L_ * DK_;
    const __nv_bfloat16* vl = g_v_lo + bh * L_ * DK_;

    const int kv_r0 = tid >> 3;
    const int kv_c = tid & 7;

    auto load_kv = [&](int p, int c0) {
        uint32_t base = sb + O_STG + p * 32768;
        #pragma unroll
        for (int i = 0; i < 2; i++) {
            int r = kv_r0 + i * 32;
            size_t so = (size_t)(c0 + r) * DK_ + kv_c * 8;
            uint32_t doff = (uint32_t)(r * 128 + ((kv_c ^ (r & 7)) << 4));
            cp16(base + doff, kh + so);
            cp16(base + 8192 + doff, kl + so);
            cp16(base + 16384 + doff, vh + so);
            cp16(base + 24576 + doff, vl + so);
        }
        CP_COMMIT();
    };

    const int rq = 16 * w + (L & 7) + ((L >> 3) & 1) * 8;
    const int rk_sub = ((L >> 4) & 1) * 8 + (L & 7);
    const int rv_sub = ((L >> 3) & 1) * 8 + (L & 7);
    const int chq_sub = (L >> 4) & 1;
    const int chk_sub = (L >> 3) & 1;
    const int chv_sub = (L >> 4) & 1;

    const int r1 = 16 * w + (L >> 2);
    const unsigned* mp1 = g_mask + (size_t)(b * L_ + q0 + r1) * (L_ / 32);
    const unsigned* mp2 = mp1 + 8 * (L_ / 32);

    float o[8][4];
    #pragma unroll
    for (int t = 0; t < 8; t++)
        #pragma unroll
        for (int e = 0; e < 4; e++) o[t][e] = 0.f;
    float rs1 = 0.f, rs2 = 0.f;

    load_kv(0, 0);

    #pragma unroll 1
    for (int it = 0; it < L_ / CT; it++) {
        int p = it & 1;
        int c0 = it * CT;
        CP_WAIT0();
        __syncthreads();
        if (it + 1 < L_ / CT) load_kv(p ^ 1, c0 + CT);

        const uint32_t kb_h = sb + O_STG + p * 32768;
        const uint32_t kb_l = kb_h + 8192;
        const uint32_t vb_h = kb_h + 16384;
        const uint32_t vb_l = kb_h + 24576;

        float s[8][4];
        #pragma unroll
        for (int t = 0; t < 8; t++)
            #pragma unroll
            for (int e = 0; e < 4; e++) s[t][e] = 0.f;

        #pragma unroll
        for (int g = 0; g < 4; g++) {
            uint32_t qh_[4], ql_[4];
            int chq = 2 * g + chq_sub;
            uint32_t qoff = (uint32_t)(rq * 128 + ((chq ^ (rq & 7)) << 4));
            ldsm4(qh_, sb + O_QHI + qoff);
            ldsm4(ql_, sb + O_QLO + qoff);
            #pragma unroll
            for (int tp = 0; tp < 4; tp++) {
                uint32_t kh_[4], kl_[4];
                int rk = 16 * tp + rk_sub;
                int chk = 2 * g + chk_sub;
                uint32_t koff = (uint32_t)(rk * 128 + ((chk ^ (rk & 7)) << 4));
                ldsm4(kh_, kb_h + koff);
                ldsm4(kl_, kb_l + koff);
                mma_bf16(s[2 * tp],     qh_, kh_);
                mma_bf16(s[2 * tp + 1], qh_, kh_ + 2);
                mma_bf16(s[2 * tp],     qh_, kl_);
                mma_bf16(s[2 * tp + 1], qh_, kl_ + 2);
                mma_bf16(s[2 * tp],     ql_, kh_);
                mma_bf16(s[2 * tp + 1], ql_, kh_ + 2);
            }
        }

        uint2 mwa = *(const uint2*)(mp1 + (c0 >> 5));
        uint2 mwb = *(const uint2*)(mp2 + (c0 >> 5));
        uint32_t ahi[4][4], alo[4][4];
        #pragma unroll
        for (int t = 0; t < 8; t++) {
            unsigned wa = (t < 4) ? mwa.x : mwa.y;
            unsigned wb = (t < 4) ? mwb.x : mwb.y;
            int sh = ((t & 3) << 3) + ((L & 3) << 1);
            float p0 = ((wa >> sh) & 1u)       ? __expf(s[t][0] * 0.125f) : 0.f;
            float p1 = ((wa >> (sh + 1)) & 1u) ? __expf(s[t][1] * 0.125f) : 0.f;
            float p2 = ((wb >> sh) & 1u)       ? __expf(s[t][2] * 0.125f) : 0.f;
            float p3 = ((wb >> (sh + 1)) & 1u) ? __expf(s[t][3] * 0.125f) : 0.f;
            rs1 += p0 + p1;
            rs2 += p2 + p3;
            float h0 = __bfloat162float(__float2bfloat16_rn(p0));
            float h1 = __bfloat162float(__float2bfloat16_rn(p1));
            float h2 = __bfloat162float(__float2bfloat16_rn(p2));
            float h3 = __bfloat162float(__float2bfloat16_rn(p3));
            int g = t >> 1, e = (t & 1) * 2;
            ahi[g][e]     = pack_bf16(h0, h1);
            ahi[g][e + 1] = pack_bf16(h2, h3);
            alo[g][e]     = pack_bf16(p0 - h0, p1 - h1);
            alo[g][e + 1] = pack_bf16(p2 - h2, p3 - h3);
        }

        #pragma unroll
        for (int g = 0; g < 4; g++) {
            int rv = 16 * g + rv_sub;
            #pragma unroll
            for (int tp = 0; tp < 4; tp++) {
                uint32_t vh_[4], vl_[4];
                int chv = 2 * tp + chv_sub;
                uint32_t voff = (uint32_t)(rv * 128 + ((chv ^ (rv & 7)) << 4));
                ldsm4t(vh_, vb_h + voff);
                ldsm4t(vl_, vb_l + voff);
                mma_bf16(o[2 * tp],     ahi[g], vh_);
                mma_bf16(o[2 * tp + 1], ahi[g], vh_ + 2);
                mma_bf16(o[2 * tp],     ahi[g], vl_);
                mma_bf16(o[2 * tp + 1], ahi[g], vl_ + 2);
                mma_bf16(o[2 * tp],     alo[g], vh_);
                mma_bf16(o[2 * tp + 1], alo[g], vh_ + 2);
            }
        }
    }

    rs1 += __shfl_xor_sync(0xffffffffu, rs1, 1);
    rs1 += __shfl_xor_sync(0xffffffffu, rs1, 2);
    rs2 += __shfl_xor_sync(0xffffffffu, rs2, 1);
    rs2 += __shfl_xor_sync(0xffffffffu, rs2, 2);
    float i1 = 1.f / rs1;
    float i2 = 1.f / rs2;

    size_t row1 = (size_t)(b * L_ + q0 + r1) * D_ + h * DK_;
    size_t row2 = row1 + 8 * D_;
    #pragma unroll
    for (int t = 0; t < 8; t++) {
        int j = 8 * t + ((L & 3) << 1);
        float v0 = o[t][0] * i1, v1 = o[t][1] * i1;
        float v2 = o[t][2] * i2, v3 = o[t][3] * i2;
        float h0 = __bfloat162float(__float2bfloat16_rn(v0));
        float h1 = __bfloat162float(__float2bfloat16_rn(v1));
        float h2 = __bfloat162float(__float2bfloat16_rn(v2));
        float h3 = __bfloat162float(__float2bfloat16_rn(v3));
        ((uint32_t*)g_mo_hi)[(row1 + j) >> 1] = pack_bf16(h0, h1);
        ((uint32_t*)g_mo_lo)[(row1 + j) >> 1] = pack_bf16(v0 - h0, v1 - h1);
        ((uint32_t*)g_mo_hi)[(row2 + j) >> 1] = pack_bf16(h2, h3);
        ((uint32_t*)g_mo_lo)[(row2 + j) >> 1] = pack_bf16(v2 - h2, v3 - h3);
    }
}

// ---------------------------------------------------------------------------
extern "C" void kernel_launch(void* const* d_in, const int* in_sizes, int n_in,
                              void* d_out, int out_size) {
    const float* q   = (const float*)d_in[0];
    const float* k   = (const float*)d_in[1];
    const float* v   = (const float*)d_in[2];
    const int*   msk = (const int*)d_in[3];
    const float* Wq  = (const float*)d_in[4];
    const float* Wk  = (const float*)d_in[5];
    const float* Wv  = (const float*)d_in[6];
    const float* Wo  = (const float*)d_in[7];
    const float* bo  = (const float*)d_in[8];
    float* out = (float*)d_out;

    cudaFuncSetAttribute(attn_mma_kernel,
                         cudaFuncAttributeMaxDynamicSharedMemorySize, ATTN_SMEM);
    cudaFuncSetAttribute(gemm_tc_kernel,
                         cudaFuncAttributeMaxDynamicSharedMemorySize, GEMM_SMEM);

    pack_mask_kernel<<<(B_ * L_ * L_) / 1024, 256>>>(msk);

    const int n4_in = (B_ * L_ * D_) / 4;
    const int n4_w  = (D_ * D_) / 4;
    conv_kernel<<<dim3(n4_in / 512, 3), 256>>>((const float4*)q, (const float4*)k,
                                               (const float4*)v, nullptr, 0, n4_in);
    conv_kernel<<<dim3(n4_w / 512, 4), 256>>>((const float4*)Wq, (const float4*)Wk,
                                              (const float4*)Wv, (const float4*)Wo, 1, n4_w);

    gemm_tc_kernel<<<dim3(D_ / 128, (B_ * L_) / 128, 3), 256, GEMM_SMEM>>>(nullptr, nullptr, 0);

    attn_mma_kernel<<<dim3(L_ / QT, H_, B_), 256, ATTN_SMEM>>>();

    gemm_tc_kernel<<<dim3(D_ / 128, (B_ * L_) / 128, 1), 256, GEMM_SMEM>>>(bo, out, 1);
}